// round 12
// baseline (speedup 1.0000x reference)
#include <cuda_runtime.h>
#include <cuda_fp16.h>
#include <cstdint>
#include <math.h>

#define BB 256
#define TT 40
#define DD 100
#define D2 200
#define NNODE 200000
#define NTYPE 1000
#define NOUT 199999   // N_NODE - 1
#define KP 256        // padded K layout for phase 2
#define NSQ 10496     // 256*40 seq rows + 256 last rows (= 82*128)

// device-global scratch (no allocation allowed)
__device__ __align__(16) __half g_emb16[(size_t)NNODE * 128];   // 51.2 MB
__device__ __align__(16) __half g_embt16[(size_t)NTYPE * 128];  // 256 KB
__device__ __align__(16) __half g_ma16[BB * KP];                // 128 KB
__device__ __align__(16) float  g_sq[(size_t)NSQ * D2];         // 8.4 MB
__device__ __align__(16) float  g_sw[(size_t)NSQ * D2];         // 8.4 MB

// ---------------------------------------------------------------------------
// helpers
// ---------------------------------------------------------------------------
__device__ __forceinline__ float tf32_of(float x) {
    uint32_t u;
    asm("cvt.rna.tf32.f32 %0, %1;" : "=r"(u) : "f"(x));
    return __uint_as_float(u);
}

__device__ __forceinline__ void mma_tf32(float d[4],
                                         uint32_t a0, uint32_t a1, uint32_t a2, uint32_t a3,
                                         uint32_t b0, uint32_t b1) {
    asm volatile(
        "mma.sync.aligned.m16n8k8.row.col.f32.tf32.tf32.f32 "
        "{%0,%1,%2,%3}, {%4,%5,%6,%7}, {%8,%9}, {%0,%1,%2,%3};\n"
        : "+f"(d[0]), "+f"(d[1]), "+f"(d[2]), "+f"(d[3])
        : "r"(a0), "r"(a1), "r"(a2), "r"(a3), "r"(b0), "r"(b1));
}

__device__ __forceinline__ void mma_f16(float d[4],
                                        uint32_t a0, uint32_t a1, uint32_t a2, uint32_t a3,
                                        uint32_t b0, uint32_t b1) {
    asm volatile(
        "mma.sync.aligned.m16n8k16.row.col.f32.f16.f16.f32 "
        "{%0,%1,%2,%3}, {%4,%5,%6,%7}, {%8,%9}, {%0,%1,%2,%3};\n"
        : "+f"(d[0]), "+f"(d[1]), "+f"(d[2]), "+f"(d[3])
        : "r"(a0), "r"(a1), "r"(a2), "r"(a3), "r"(b0), "r"(b1));
}

__device__ __forceinline__ void ldsm_x4(uint32_t& r0, uint32_t& r1,
                                        uint32_t& r2, uint32_t& r3, uint32_t addr) {
    asm volatile("ldmatrix.sync.aligned.m8n8.x4.shared.b16 {%0,%1,%2,%3}, [%4];"
                 : "=r"(r0), "=r"(r1), "=r"(r2), "=r"(r3) : "r"(addr));
}

__device__ __forceinline__ void cp16(uint32_t dst, const void* src) {
    asm volatile("cp.async.cg.shared.global [%0], [%1], 16;"
                 :: "r"(dst), "l"(src) : "memory");
}
__device__ __forceinline__ void cp_commit() {
    asm volatile("cp.async.commit_group;" ::: "memory");
}
template <int N>
__device__ __forceinline__ void cp_wait() {
    asm volatile("cp.async.wait_group %0;" :: "n"(N) : "memory");
}

__device__ __forceinline__ uint4 h8_of(float4 a, float4 b) {
    __half2 h0 = __float22half2_rn(make_float2(a.x, a.y));
    __half2 h1 = __float22half2_rn(make_float2(a.z, a.w));
    __half2 h2 = __float22half2_rn(make_float2(b.x, b.y));
    __half2 h3 = __float22half2_rn(make_float2(b.z, b.w));
    uint4 u;
    u.x = *reinterpret_cast<uint32_t*>(&h0);
    u.y = *reinterpret_cast<uint32_t*>(&h1);
    u.z = *reinterpret_cast<uint32_t*>(&h2);
    u.w = *reinterpret_cast<uint32_t*>(&h3);
    return u;
}

// ---------------------------------------------------------------------------
// prep: fp32 -> fp16 padded copies of embedding tables
// ---------------------------------------------------------------------------
#define EMB_UNITS (NNODE * 16)
#define EMBT_UNITS (NTYPE * 16)

__global__ __launch_bounds__(256) void prep_kernel(
    const float* __restrict__ emb, const float* __restrict__ embt)
{
    int uid = blockIdx.x * 256 + threadIdx.x;
    const float4 z = make_float4(0.f, 0.f, 0.f, 0.f);
    if (uid < EMB_UNITS) {
        int row = uid >> 4, u = uid & 15;
        int fb = 8 * u;
        const float4* src = (const float4*)(emb + (size_t)row * DD);
        float4 f0 = (fb < DD) ? src[fb >> 2] : z;
        float4 f1 = (fb + 4 < DD) ? src[(fb >> 2) + 1] : z;
        *(uint4*)(g_emb16 + (size_t)row * 128 + fb) = h8_of(f0, f1);
    } else if (uid < EMB_UNITS + EMBT_UNITS) {
        int t = uid - EMB_UNITS;
        int row = t >> 4, u = t & 15;
        int fb = 8 * u;
        const float4* src = (const float4*)(embt + (size_t)row * DD);
        float4 f0 = (fb < DD) ? src[fb >> 2] : z;
        float4 f1 = (fb + 4 < DD) ? src[(fb >> 2) + 1] : z;
        *(uint4*)(g_embt16 + (size_t)row * 128 + fb) = h8_of(f0, f1);
    }
}

// ---------------------------------------------------------------------------
// p1a: gather seq_htype + last rows into g_sq
//   rows b*40+t   : [re[b,alias[b,t]] | ret[b,aliast[b,t]]]
//   row  10240+b  : last vector
// ---------------------------------------------------------------------------
__global__ __launch_bounds__(256) void p1a_gather(
    const float* __restrict__ re, const float* __restrict__ ret,
    const float* __restrict__ mask, const float* __restrict__ maskt,
    const int* __restrict__ alias, const int* __restrict__ aliast)
{
    __shared__ int sa[TT], sat[TT], slast[2];
    const int b = blockIdx.x;
    const int tid = threadIdx.x;

    if (tid < TT) {
        sa[tid]  = alias[b * TT + tid];
        sat[tid] = aliast[b * TT + tid];
    }
    if (tid == 0) {
        float s = 0.f, st = 0.f;
        for (int t = 0; t < TT; t++) { s += mask[b * TT + t]; st += maskt[b * TT + t]; }
        int rm  = (int)(s  + 0.5f); rm  = rm  < 1 ? 1 : (rm  > TT ? TT : rm);
        int rmt = (int)(st + 0.5f); rmt = rmt < 1 ? 1 : (rmt > TT ? TT : rmt);
        slast[0] = alias[b * TT + rm - 1];
        slast[1] = aliast[b * TT + rmt - 1];
    }
    __syncthreads();

    for (int idx = tid; idx < TT * D2; idx += 256) {
        int t = idx / D2, k = idx - t * D2;
        g_sq[(size_t)(b * TT + t) * D2 + k] =
            (k < DD) ? re[(b * TT + sa[t]) * DD + k]
                     : ret[(b * TT + sat[t]) * DD + (k - DD)];
    }
    if (tid < D2) {
        g_sq[(size_t)(10240 + b) * D2 + tid] =
            (tid < DD) ? re[(b * TT + slast[0]) * DD + tid]
                       : ret[(b * TT + slast[1]) * DD + (tid - DD)];
    }
}

// ---------------------------------------------------------------------------
// p1b: g_sw = g_sq @ W  (tf32 mma, R5-verified fragment scheme)
//   m-tiles 0..79 -> W = w2 ; m-tiles 80..81 -> W = w1
//   K = 200 in two 104-pad halves, SM_STRIDE = 108.
// ---------------------------------------------------------------------------
#define SM_STRIDE 108

__global__ __launch_bounds__(256, 2) void p1b_gemm(
    const float* __restrict__ w1, const float* __restrict__ w2)
{
    extern __shared__ float smB[];
    float* As = smB;                      // [128][108]
    float* Bs = smB + 128 * SM_STRIDE;    // [128][108]

    const int tid  = threadIdx.x;
    const int n0   = blockIdx.x * 128;    // output col tile (0 or 128)
    const int mt_i = blockIdx.y;          // m tile 0..81
    const int m0   = mt_i * 128;
    const float* W = (mt_i < 80) ? w2 : w1;
    const int lane = tid & 31;
    const int warp = tid >> 5;
    const int wm = warp >> 2;
    const int wn = warp & 3;

    float acc[4][4][4];
#pragma unroll
    for (int mt = 0; mt < 4; mt++)
#pragma unroll
        for (int nt = 0; nt < 4; nt++)
#pragma unroll
            for (int r = 0; r < 4; r++) acc[mt][nt][r] = 0.f;

    for (int h = 0; h < 2; h++) {
        __syncthreads();

        // A half: g_sq[m0..+127][h*100..+99] -> tf32
        for (int idx = tid; idx < 128 * 25; idx += 256) {
            int r = idx / 25, c = idx % 25;
            float4 a = *(const float4*)(g_sq + (size_t)(m0 + r) * D2 + h * DD + c * 4);
            float4 w;
            w.x = tf32_of(a.x); w.y = tf32_of(a.y);
            w.z = tf32_of(a.z); w.w = tf32_of(a.w);
            *(float4*)(As + r * SM_STRIDE + c * 4) = w;
        }
        for (int i = tid; i < 128; i += 256)
            *(float4*)(As + i * SM_STRIDE + 100) = make_float4(0.f, 0.f, 0.f, 0.f);

        // B half: Bs[n][kk] = W[(h*100+kk)*200 + n0+n] (transpose at staging)
        for (int idx = tid; idx < 128 * 100; idx += 256) {
            int kk = idx >> 7, n = idx & 127;
            float val = (n0 + n < D2) ? W[(size_t)(h * DD + kk) * D2 + n0 + n] : 0.f;
            Bs[n * SM_STRIDE + kk] = tf32_of(val);
        }
        for (int i = tid; i < 128; i += 256)
            *(float4*)(Bs + i * SM_STRIDE + 100) = make_float4(0.f, 0.f, 0.f, 0.f);

        __syncthreads();

        const float* ab = As + (wm * 64 + (lane >> 2)) * SM_STRIDE + (lane & 3);
        const float* bb = Bs + (wn * 32 + (lane >> 2)) * SM_STRIDE + (lane & 3);

#pragma unroll
        for (int ks = 0; ks < 13; ks++) {
            const int k0 = ks * 8;
            uint32_t af[4][4], bf[4][2];
#pragma unroll
            for (int mt = 0; mt < 4; mt++) {
                const float* p = ab + mt * 16 * SM_STRIDE + k0;
                af[mt][0] = __float_as_uint(p[0]);
                af[mt][1] = __float_as_uint(p[8 * SM_STRIDE]);
                af[mt][2] = __float_as_uint(p[4]);
                af[mt][3] = __float_as_uint(p[8 * SM_STRIDE + 4]);
            }
#pragma unroll
            for (int nt = 0; nt < 4; nt++) {
                const float* p = bb + nt * 8 * SM_STRIDE + k0;
                bf[nt][0] = __float_as_uint(p[0]);
                bf[nt][1] = __float_as_uint(p[4]);
            }
#pragma unroll
            for (int mt = 0; mt < 4; mt++)
#pragma unroll
                for (int nt = 0; nt < 4; nt++)
                    mma_tf32(acc[mt][nt],
                             af[mt][0], af[mt][1], af[mt][2], af[mt][3],
                             bf[nt][0], bf[nt][1]);
        }
    }

#pragma unroll
    for (int mt = 0; mt < 4; mt++) {
        int r = m0 + wm * 64 + mt * 16 + (lane >> 2);
#pragma unroll
        for (int nt = 0; nt < 4; nt++) {
            int c = n0 + wn * 32 + nt * 8 + 2 * (lane & 3);
            if (c < D2) {
                g_sw[(size_t)r * D2 + c]       = acc[mt][nt][0];
                g_sw[(size_t)(r + 8) * D2 + c] = acc[mt][nt][2];
                if (c + 1 < D2) {
                    g_sw[(size_t)r * D2 + c + 1]       = acc[mt][nt][1];
                    g_sw[(size_t)(r + 8) * D2 + c + 1] = acc[mt][nt][3];
                }
            }
        }
    }
}

// ---------------------------------------------------------------------------
// p1c: epilogue — sigmoid/coef/weighted-sum/w3 -> g_ma16 (padded fp16)
// ---------------------------------------------------------------------------
__global__ __launch_bounds__(256) void p1c_epilogue(
    const float* __restrict__ mask,
    const float* __restrict__ w3,
    const float* __restrict__ v,
    const float* __restrict__ bias)
{
    extern __shared__ float smc[];
    float* cbuf  = smc;            // [40][200]
    float* coefs = smc + 8000;     // [40]
    float* svec  = smc + 8040;     // [200]

    const int b = blockIdx.x;
    const int tid = threadIdx.x;
    const int lane = tid & 31;
    const int warp = tid >> 5;
    const int j = tid;

    g_ma16[b * KP + tid] = __float2half(0.f);  // zero padded row

    if (j < D2) {
        const float lw = g_sw[(size_t)(10240 + b) * D2 + j];
        const float vj = v[j], bj = bias[j];
        const float base = lw + bj;
#pragma unroll 4
        for (int t = 0; t < TT; t++) {
            float x = base + g_sw[(size_t)(b * TT + t) * D2 + j];
            float e = __expf(-x);
            cbuf[t * D2 + j] = __fdividef(vj, 1.f + e);
        }
    }
    __syncthreads();

    // coef[t]: 8 warps x 5 t each, warp-shfl reduce over 200 j
    for (int t = warp; t < TT; t += 8) {
        float c = 0.f;
        for (int jj = lane; jj < D2; jj += 32) c += cbuf[t * D2 + jj];
#pragma unroll
        for (int o = 16; o > 0; o >>= 1) c += __shfl_xor_sync(0xFFFFFFFFu, c, o);
        if (lane == 0) coefs[t] = c * mask[b * TT + t];
    }
    __syncthreads();

    if (tid < D2) {
        float s = 0.f;
#pragma unroll
        for (int t = 0; t < TT; t++)
            s += coefs[t] * g_sq[(size_t)(b * TT + t) * D2 + tid];
        svec[tid] = s;
    }
    __syncthreads();

    if (j < D2) {
        float m = 0.f;
        for (int k = 0; k < D2; k++) m += svec[k] * w3[(size_t)k * D2 + j];
        int pos = (j < DD) ? j : (j + 28);
        g_ma16[b * KP + pos] = __float2half(m);
    }
}

// ---------------------------------------------------------------------------
// Phase 2: logits = ma16 @ b_emb16^T, fp16 mma.m16n8k16 (unchanged from R11)
// ---------------------------------------------------------------------------
#define CHB   128
#define TILEB (128 * CHB)
#define BUFB  (2 * TILEB)
#define SCT_OFF 67584
#define P2_SMEM (SCT_OFF + 512)
#define CSTR  132

__global__ __launch_bounds__(256, 2) void phase2_impl(
    const int* __restrict__ csort,
    float* __restrict__ out)
{
    extern __shared__ __align__(16) float sm2[];
    const uint32_t sb = (uint32_t)__cvta_generic_to_shared(sm2);
    int* sct = (int*)((char*)sm2 + SCT_OFF);

    const int tid  = threadIdx.x;
    const int wid  = tid >> 5;
    const int lane = tid & 31;
    const int m0   = blockIdx.x * 128;
    const int n0   = blockIdx.y * 128;
    const int wm = wid >> 2;
    const int wn = wid & 3;

    for (int i = tid; i < 128; i += 256) {
        int n = n0 + i + 1; if (n > NNODE - 1) n = NNODE - 1;
        sct[i] = csort[n];
    }
    __syncthreads();

    const int hiA = (lane >> 4) & 1;
    const int hiB = (lane >> 3) & 1;
    int rowAoff[4], swA[4], rowBoff[2], swB[2];
#pragma unroll
    for (int mt = 0; mt < 4; mt++) {
        int r = wm * 64 + mt * 16 + (lane & 15);
        rowAoff[mt] = r * CHB; swA[mt] = r & 7;
    }
#pragma unroll
    for (int p = 0; p < 2; p++) {
        int r = wn * 32 + p * 16 + ((lane >> 4) & 1) * 8 + (lane & 7);
        rowBoff[p] = r * CHB; swB[p] = r & 7;
    }

    float acc[4][4][4];
#pragma unroll
    for (int mt = 0; mt < 4; mt++)
#pragma unroll
        for (int nt = 0; nt < 4; nt++)
#pragma unroll
            for (int r = 0; r < 4; r++) acc[mt][nt][r] = 0.f;

    auto issue_chunk = [&](int c) {
        const uint32_t buf = sb + (uint32_t)((c & 1) * BUFB);
#pragma unroll
        for (int i = 0; i < 8; i++) {
            int uid = tid + i * 256;
            int tile = uid >> 10;
            int r = (uid >> 3) & 127;
            int u = uid & 7;
            uint32_t dst = buf + (uint32_t)(tile * TILEB + r * CHB
                                            + ((u ^ (r & 7)) << 4));
            const __half* src;
            if (tile == 0) {
                src = g_ma16 + (size_t)(m0 + r) * KP + c * 64 + u * 8;
            } else if (c < 2) {
                int n = n0 + r + 1; if (n > NNODE - 1) n = NNODE - 1;
                src = g_emb16 + (size_t)n * 128 + c * 64 + u * 8;
            } else {
                src = g_embt16 + (size_t)sct[r] * 128 + (c - 2) * 64 + u * 8;
            }
            cp16(dst, src);
        }
        cp_commit();
    };

    issue_chunk(0);
    issue_chunk(1);

#pragma unroll
    for (int c = 0; c < 4; c++) {
        if (c < 3) cp_wait<1>(); else cp_wait<0>();
        __syncthreads();

        const uint32_t bufo = (uint32_t)((c & 1) * BUFB);
#pragma unroll
        for (int ks = 0; ks < 4; ks++) {
            uint32_t af[4][4], bf[4][2];
            const int uA = 2 * ks + hiA;
            const int uB = 2 * ks + hiB;
#pragma unroll
            for (int mt = 0; mt < 4; mt++) {
                uint32_t addr = sb + bufo + (uint32_t)rowAoff[mt]
                              + (uint32_t)((uA ^ swA[mt]) << 4);
                ldsm_x4(af[mt][0], af[mt][1], af[mt][2], af[mt][3], addr);
            }
#pragma unroll
            for (int p = 0; p < 2; p++) {
                uint32_t addr = sb + bufo + (uint32_t)TILEB + (uint32_t)rowBoff[p]
                              + (uint32_t)((uB ^ swB[p]) << 4);
                uint32_t r0, r1, r2, r3;
                ldsm_x4(r0, r1, r2, r3, addr);
                bf[2 * p][0] = r0;     bf[2 * p][1] = r1;
                bf[2 * p + 1][0] = r2; bf[2 * p + 1][1] = r3;
            }
#pragma unroll
            for (int mt = 0; mt < 4; mt++)
#pragma unroll
                for (int nt = 0; nt < 4; nt++)
                    mma_f16(acc[mt][nt],
                            af[mt][0], af[mt][1], af[mt][2], af[mt][3],
                            bf[nt][0], bf[nt][1]);
        }
        __syncthreads();
        if (c < 2) issue_chunk(c + 2);
    }

    float* Cs = sm2;
#pragma unroll
    for (int mt = 0; mt < 4; mt++) {
        int r1 = wm * 64 + mt * 16 + (lane >> 2);
#pragma unroll
        for (int nt = 0; nt < 4; nt++) {
            int cc = wn * 32 + nt * 8 + 2 * (lane & 3);
            Cs[r1 * CSTR + cc]           = acc[mt][nt][0];
            Cs[r1 * CSTR + cc + 1]       = acc[mt][nt][1];
            Cs[(r1 + 8) * CSTR + cc]     = acc[mt][nt][2];
            Cs[(r1 + 8) * CSTR + cc + 1] = acc[mt][nt][3];
        }
    }
    __syncthreads();

    for (int idx = tid; idx < 128 * 128; idx += 256) {
        int r = idx >> 7, cc = idx & 127;
        int n = n0 + cc;
        if (n < NOUT)
            out[(size_t)(m0 + r) * NOUT + n] = Cs[r * CSTR + cc];
    }
}

// ---------------------------------------------------------------------------
// launch
// ---------------------------------------------------------------------------
extern "C" void kernel_launch(void* const* d_in, const int* in_sizes, int n_in,
                              void* d_out, int out_size) {
    (void)in_sizes; (void)n_in; (void)out_size;
    const float* re     = (const float*)d_in[0];
    const float* ret    = (const float*)d_in[1];
    const float* mask   = (const float*)d_in[2];
    const float* maskt  = (const float*)d_in[3];
    const int*   alias  = (const int*)d_in[4];
    const int*   aliast = (const int*)d_in[5];
    const int*   csort  = (const int*)d_in[6];
    const float* emb    = (const float*)d_in[7];
    const float* embt   = (const float*)d_in[8];
    const float* w1     = (const float*)d_in[9];
    const float* w2     = (const float*)d_in[10];
    const float* w3     = (const float*)d_in[11];
    const float* v      = (const float*)d_in[12];
    const float* bias   = (const float*)d_in[13];
    float* out = (float*)d_out;

    const size_t smB = (size_t)(2 * 128 * SM_STRIDE) * sizeof(float);  // 110,592 B
    const size_t smC = (size_t)8240 * sizeof(float);                   // 32,960 B
    const size_t sm2 = (size_t)P2_SMEM;                                // 68,096 B
    cudaFuncSetAttribute(p1b_gemm, cudaFuncAttributeMaxDynamicSharedMemorySize, (int)smB);
    cudaFuncSetAttribute(p1c_epilogue, cudaFuncAttributeMaxDynamicSharedMemorySize, (int)smC);
    cudaFuncSetAttribute(phase2_impl, cudaFuncAttributeMaxDynamicSharedMemorySize, (int)sm2);

    const int prep_blocks = (EMB_UNITS + EMBT_UNITS + 255) / 256;
    prep_kernel<<<prep_blocks, 256>>>(emb, embt);

    p1a_gather<<<BB, 256>>>(re, ret, mask, maskt, alias, aliast);

    dim3 gridB(2, 82, 1);
    p1b_gemm<<<gridB, 256, smB>>>(w1, w2);

    p1c_epilogue<<<BB, 256, smC>>>(mask, w3, v, bias);

    dim3 grid2(2, (NOUT + 127) / 128, 1);
    phase2_impl<<<grid2, 256, sm2>>>(csort, out);
}

// round 13
// speedup vs baseline: 1.2070x; 1.2070x over previous
#include <cuda_runtime.h>
#include <cuda_fp16.h>
#include <cstdint>
#include <math.h>

#define BB 256
#define TT 40
#define DD 100
#define D2 200
#define NNODE 200000
#define NTYPE 1000
#define NOUT 199999   // N_NODE - 1
#define KP 256        // padded K layout for phase 2

// device-global scratch (no allocation allowed)
__device__ __align__(16) __half g_emb16[(size_t)NNODE * 128];   // 51.2 MB
__device__ __align__(16) __half g_embt16[(size_t)NTYPE * 128];  // 256 KB
__device__ __align__(16) __half g_ma16[BB * KP];                // 128 KB

// ---------------------------------------------------------------------------
// helpers
// ---------------------------------------------------------------------------
__device__ __forceinline__ void mma_f16(float d[4],
                                        uint32_t a0, uint32_t a1, uint32_t a2, uint32_t a3,
                                        uint32_t b0, uint32_t b1) {
    asm volatile(
        "mma.sync.aligned.m16n8k16.row.col.f32.f16.f16.f32 "
        "{%0,%1,%2,%3}, {%4,%5,%6,%7}, {%8,%9}, {%0,%1,%2,%3};\n"
        : "+f"(d[0]), "+f"(d[1]), "+f"(d[2]), "+f"(d[3])
        : "r"(a0), "r"(a1), "r"(a2), "r"(a3), "r"(b0), "r"(b1));
}

__device__ __forceinline__ void ldsm_x4(uint32_t& r0, uint32_t& r1,
                                        uint32_t& r2, uint32_t& r3, uint32_t addr) {
    asm volatile("ldmatrix.sync.aligned.m8n8.x4.shared.b16 {%0,%1,%2,%3}, [%4];"
                 : "=r"(r0), "=r"(r1), "=r"(r2), "=r"(r3) : "r"(addr));
}

__device__ __forceinline__ void cp16(uint32_t dst, const void* src) {
    asm volatile("cp.async.cg.shared.global [%0], [%1], 16;"
                 :: "r"(dst), "l"(src) : "memory");
}
__device__ __forceinline__ void cp_commit() {
    asm volatile("cp.async.commit_group;" ::: "memory");
}
template <int N>
__device__ __forceinline__ void cp_wait() {
    asm volatile("cp.async.wait_group %0;" :: "n"(N) : "memory");
}

__device__ __forceinline__ uint4 h8_of(float4 a, float4 b) {
    __half2 h0 = __float22half2_rn(make_float2(a.x, a.y));
    __half2 h1 = __float22half2_rn(make_float2(a.z, a.w));
    __half2 h2 = __float22half2_rn(make_float2(b.x, b.y));
    __half2 h3 = __float22half2_rn(make_float2(b.z, b.w));
    uint4 u;
    u.x = *reinterpret_cast<uint32_t*>(&h0);
    u.y = *reinterpret_cast<uint32_t*>(&h1);
    u.z = *reinterpret_cast<uint32_t*>(&h2);
    u.w = *reinterpret_cast<uint32_t*>(&h3);
    return u;
}

// ---------------------------------------------------------------------------
// prep: fp32 -> fp16 padded copies of embedding tables (passing, R11)
// ---------------------------------------------------------------------------
#define EMB_UNITS (NNODE * 16)
#define EMBT_UNITS (NTYPE * 16)

__global__ __launch_bounds__(256) void prep_kernel(
    const float* __restrict__ emb, const float* __restrict__ embt)
{
    int uid = blockIdx.x * 256 + threadIdx.x;
    const float4 z = make_float4(0.f, 0.f, 0.f, 0.f);
    if (uid < EMB_UNITS) {
        int row = uid >> 4, u = uid & 15;
        int fb = 8 * u;
        const float4* src = (const float4*)(emb + (size_t)row * DD);
        float4 f0 = (fb < DD) ? src[fb >> 2] : z;
        float4 f1 = (fb + 4 < DD) ? src[(fb >> 2) + 1] : z;
        *(uint4*)(g_emb16 + (size_t)row * 128 + fb) = h8_of(f0, f1);
    } else if (uid < EMB_UNITS + EMBT_UNITS) {
        int t = uid - EMB_UNITS;
        int row = t >> 4, u = t & 15;
        int fb = 8 * u;
        const float4* src = (const float4*)(embt + (size_t)row * DD);
        float4 f0 = (fb < DD) ? src[fb >> 2] : z;
        float4 f1 = (fb + 4 < DD) ? src[(fb >> 2) + 1] : z;
        *(uint4*)(g_embt16 + (size_t)row * 128 + fb) = h8_of(f0, f1);
    }
}

// ---------------------------------------------------------------------------
// Phase 1: one CTA of 512 threads per batch element.
// Warps 0-7 own t=0..19, warps 8-15 own t=20..39 (acc[20] per thread).
// Writes g_ma16[b][.] in padded fp16 layout.
// ---------------------------------------------------------------------------
__global__ __launch_bounds__(512) void phase1_kernel(
    const float* __restrict__ re,     // [B,U,D]
    const float* __restrict__ ret,    // [B,U,D]
    const float* __restrict__ mask,   // [B,T]
    const float* __restrict__ maskt,  // [B,T]
    const int*   __restrict__ alias,  // [B,T]
    const int*   __restrict__ aliast, // [B,T]
    const float* __restrict__ w1,     // [2D,2D]
    const float* __restrict__ w2,     // [2D,2D]
    const float* __restrict__ w3,     // [2D,2D]
    const float* __restrict__ v,      // [2D]
    const float* __restrict__ bias)   // [2D]
{
    extern __shared__ float sm1[];
    float* sh    = sm1;            // [40][200]
    float* cbuf  = sm1 + 8000;     // [40][200]
    float* coefs = sm1 + 16000;    // [40]
    float* svec  = sm1 + 16040;    // [200]
    float* lastv = sm1 + 16240;    // [200]
    __shared__ int sa[TT], sat[TT], slast[2];

    const int b = blockIdx.x;
    const int tid = threadIdx.x;
    const int half = tid >> 8;      // 0: t 0..19, 1: t 20..39
    const int j = tid & 255;
    const int warp = tid >> 5;
    const int lane = tid & 31;

    if (tid < KP) g_ma16[b * KP + tid] = __float2half(0.f);

    if (tid < TT) {
        sa[tid]  = alias[b * TT + tid];
        sat[tid] = aliast[b * TT + tid];
    }
    if (tid == 0) {
        float s = 0.f, st = 0.f;
        for (int t = 0; t < TT; t++) { s += mask[b * TT + t]; st += maskt[b * TT + t]; }
        int rm  = (int)(s  + 0.5f); rm  = rm  < 1 ? 1 : (rm  > TT ? TT : rm);
        int rmt = (int)(st + 0.5f); rmt = rmt < 1 ? 1 : (rmt > TT ? TT : rmt);
        slast[0] = alias[b * TT + rm - 1];
        slast[1] = aliast[b * TT + rmt - 1];
    }
    __syncthreads();

    for (int idx = tid; idx < TT * D2; idx += 512) {
        int t = idx / D2, k = idx - t * D2;
        sh[idx] = (k < DD) ? re[(b * TT + sa[t]) * DD + k]
                           : ret[(b * TT + sat[t]) * DD + (k - DD)];
    }
    if (tid < D2) {
        lastv[tid] = (tid < DD) ? re[(b * TT + slast[0]) * DD + tid]
                                : ret[(b * TT + slast[1]) * DD + (tid - DD)];
    }
    __syncthreads();

    // last_proj[j] (both halves compute their own copy — cached w1 reads)
    float lpj = 0.f;
    if (j < D2) {
        for (int k = 0; k < D2; k++) lpj += lastv[k] * w1[k * D2 + j];
    }

    if (j < D2) {
        const int tb = half * 20;
        float acc[20];
#pragma unroll
        for (int tt = 0; tt < 20; tt++) acc[tt] = 0.f;
        for (int k = 0; k < D2; k += 4) {
            float wa = w2[(k + 0) * D2 + j];
            float wb = w2[(k + 1) * D2 + j];
            float wc = w2[(k + 2) * D2 + j];
            float wd = w2[(k + 3) * D2 + j];
#pragma unroll
            for (int tt = 0; tt < 20; tt++) {
                float4 s4 = *(const float4*)&sh[(tb + tt) * D2 + k];
                acc[tt] += s4.x * wa + s4.y * wb + s4.z * wc + s4.w * wd;
            }
        }
        float vj = v[j], bj = bias[j];
        const float base = lpj + bj;
#pragma unroll
        for (int tt = 0; tt < 20; tt++) {
            float x = base + acc[tt];
            float e = __expf(-x);
            cbuf[(tb + tt) * D2 + j] = __fdividef(vj, 1.f + e);
        }
    }
    __syncthreads();

    // coef[t]: 16 warps, shfl reduce over 200 j
    for (int t = warp; t < TT; t += 16) {
        float c = 0.f;
        for (int jj = lane; jj < D2; jj += 32) c += cbuf[t * D2 + jj];
#pragma unroll
        for (int o = 16; o > 0; o >>= 1) c += __shfl_xor_sync(0xFFFFFFFFu, c, o);
        if (lane == 0) coefs[t] = c * mask[b * TT + t];
    }
    __syncthreads();

    if (tid < D2) {
        float s = 0.f;
#pragma unroll
        for (int t = 0; t < TT; t++) s += coefs[t] * sh[t * D2 + tid];
        svec[tid] = s;
    }
    __syncthreads();

    // ma[j] = svec @ w3[:,j]; split k-range across halves, combine via smem
    if (j < D2) {
        const int k0 = half * DD;
        float m = 0.f;
        for (int k = k0; k < k0 + DD; k++) m += svec[k] * w3[(size_t)k * D2 + j];
        cbuf[half * D2 + j] = m;     // reuse cbuf as partial buffer
    }
    __syncthreads();
    if (half == 0 && j < D2) {
        float m = cbuf[j] + cbuf[D2 + j];
        int pos = (j < DD) ? j : (j + 28);
        g_ma16[b * KP + pos] = __float2half(m);
    }
}

// ---------------------------------------------------------------------------
// Phase 2: logits = ma16 @ b_emb16^T, fp16 mma.m16n8k16 (R11 core, passing)
// + streaming stores and vectorized epilogue reads.
// ---------------------------------------------------------------------------
#define CHB   128
#define TILEB (128 * CHB)
#define BUFB  (2 * TILEB)
#define SCT_OFF 67584
#define P2_SMEM (SCT_OFF + 512)
#define CSTR  132

__global__ __launch_bounds__(256, 2) void phase2_impl(
    const int* __restrict__ csort,
    float* __restrict__ out)
{
    extern __shared__ __align__(16) float sm2[];
    const uint32_t sb = (uint32_t)__cvta_generic_to_shared(sm2);
    int* sct = (int*)((char*)sm2 + SCT_OFF);

    const int tid  = threadIdx.x;
    const int wid  = tid >> 5;
    const int lane = tid & 31;
    const int m0   = blockIdx.x * 128;
    const int n0   = blockIdx.y * 128;
    const int wm = wid >> 2;
    const int wn = wid & 3;

    for (int i = tid; i < 128; i += 256) {
        int n = n0 + i + 1; if (n > NNODE - 1) n = NNODE - 1;
        sct[i] = csort[n];
    }
    __syncthreads();

    const int hiA = (lane >> 4) & 1;
    const int hiB = (lane >> 3) & 1;
    int rowAoff[4], swA[4], rowBoff[2], swB[2];
#pragma unroll
    for (int mt = 0; mt < 4; mt++) {
        int r = wm * 64 + mt * 16 + (lane & 15);
        rowAoff[mt] = r * CHB; swA[mt] = r & 7;
    }
#pragma unroll
    for (int p = 0; p < 2; p++) {
        int r = wn * 32 + p * 16 + ((lane >> 4) & 1) * 8 + (lane & 7);
        rowBoff[p] = r * CHB; swB[p] = r & 7;
    }

    float acc[4][4][4];
#pragma unroll
    for (int mt = 0; mt < 4; mt++)
#pragma unroll
        for (int nt = 0; nt < 4; nt++)
#pragma unroll
            for (int r = 0; r < 4; r++) acc[mt][nt][r] = 0.f;

    auto issue_chunk = [&](int c) {
        const uint32_t buf = sb + (uint32_t)((c & 1) * BUFB);
#pragma unroll
        for (int i = 0; i < 8; i++) {
            int uid = tid + i * 256;
            int tile = uid >> 10;
            int r = (uid >> 3) & 127;
            int u = uid & 7;
            uint32_t dst = buf + (uint32_t)(tile * TILEB + r * CHB
                                            + ((u ^ (r & 7)) << 4));
            const __half* src;
            if (tile == 0) {
                src = g_ma16 + (size_t)(m0 + r) * KP + c * 64 + u * 8;
            } else if (c < 2) {
                int n = n0 + r + 1; if (n > NNODE - 1) n = NNODE - 1;
                src = g_emb16 + (size_t)n * 128 + c * 64 + u * 8;
            } else {
                src = g_embt16 + (size_t)sct[r] * 128 + (c - 2) * 64 + u * 8;
            }
            cp16(dst, src);
        }
        cp_commit();
    };

    issue_chunk(0);
    issue_chunk(1);

#pragma unroll
    for (int c = 0; c < 4; c++) {
        if (c < 3) cp_wait<1>(); else cp_wait<0>();
        __syncthreads();

        const uint32_t bufo = (uint32_t)((c & 1) * BUFB);
#pragma unroll
        for (int ks = 0; ks < 4; ks++) {
            uint32_t af[4][4], bf[4][2];
            const int uA = 2 * ks + hiA;
            const int uB = 2 * ks + hiB;
#pragma unroll
            for (int mt = 0; mt < 4; mt++) {
                uint32_t addr = sb + bufo + (uint32_t)rowAoff[mt]
                              + (uint32_t)((uA ^ swA[mt]) << 4);
                ldsm_x4(af[mt][0], af[mt][1], af[mt][2], af[mt][3], addr);
            }
#pragma unroll
            for (int p = 0; p < 2; p++) {
                uint32_t addr = sb + bufo + (uint32_t)TILEB + (uint32_t)rowBoff[p]
                              + (uint32_t)((uB ^ swB[p]) << 4);
                uint32_t r0, r1, r2, r3;
                ldsm_x4(r0, r1, r2, r3, addr);
                bf[2 * p][0] = r0;     bf[2 * p][1] = r1;
                bf[2 * p + 1][0] = r2; bf[2 * p + 1][1] = r3;
            }
#pragma unroll
            for (int mt = 0; mt < 4; mt++)
#pragma unroll
                for (int nt = 0; nt < 4; nt++)
                    mma_f16(acc[mt][nt],
                            af[mt][0], af[mt][1], af[mt][2], af[mt][3],
                            bf[nt][0], bf[nt][1]);
        }
        __syncthreads();
        if (c < 2) issue_chunk(c + 2);
    }

    // epilogue: smem transpose -> streaming coalesced stores
    float* Cs = sm2;
#pragma unroll
    for (int mt = 0; mt < 4; mt++) {
        int r1 = wm * 64 + mt * 16 + (lane >> 2);
#pragma unroll
        for (int nt = 0; nt < 4; nt++) {
            int cc = wn * 32 + nt * 8 + 2 * (lane & 3);
            Cs[r1 * CSTR + cc]           = acc[mt][nt][0];
            Cs[r1 * CSTR + cc + 1]       = acc[mt][nt][1];
            Cs[(r1 + 8) * CSTR + cc]     = acc[mt][nt][2];
            Cs[(r1 + 8) * CSTR + cc + 1] = acc[mt][nt][3];
        }
    }
    __syncthreads();

    if (n0 + 128 <= NOUT) {
        // interior tile: LDS.128 + 4 streaming scalar stores (rows are only
        // 4B-aligned because NOUT is odd)
        for (int idx = tid; idx < 128 * 32; idx += 256) {
            int r = idx >> 5, c4 = (idx & 31) << 2;
            float4 vv = *(const float4*)&Cs[r * CSTR + c4];
            float* po = out + (size_t)(m0 + r) * NOUT + n0 + c4;
            __stcs(po + 0, vv.x);
            __stcs(po + 1, vv.y);
            __stcs(po + 2, vv.z);
            __stcs(po + 3, vv.w);
        }
    } else {
        for (int idx = tid; idx < 128 * 128; idx += 256) {
            int r = idx >> 7, cc = idx & 127;
            int n = n0 + cc;
            if (n < NOUT)
                __stcs(out + (size_t)(m0 + r) * NOUT + n, Cs[r * CSTR + cc]);
        }
    }
}

// ---------------------------------------------------------------------------
// launch
// ---------------------------------------------------------------------------
extern "C" void kernel_launch(void* const* d_in, const int* in_sizes, int n_in,
                              void* d_out, int out_size) {
    (void)in_sizes; (void)n_in; (void)out_size;
    const float* re     = (const float*)d_in[0];
    const float* ret    = (const float*)d_in[1];
    const float* mask   = (const float*)d_in[2];
    const float* maskt  = (const float*)d_in[3];
    const int*   alias  = (const int*)d_in[4];
    const int*   aliast = (const int*)d_in[5];
    const int*   csort  = (const int*)d_in[6];
    const float* emb    = (const float*)d_in[7];
    const float* embt   = (const float*)d_in[8];
    const float* w1     = (const float*)d_in[9];
    const float* w2     = (const float*)d_in[10];
    const float* w3     = (const float*)d_in[11];
    const float* v      = (const float*)d_in[12];
    const float* bias   = (const float*)d_in[13];
    float* out = (float*)d_out;

    const size_t sm1 = (size_t)16440 * sizeof(float);   // 65,760 B
    const size_t sm2 = (size_t)P2_SMEM;                 // 68,096 B
    cudaFuncSetAttribute(phase1_kernel, cudaFuncAttributeMaxDynamicSharedMemorySize, (int)sm1);
    cudaFuncSetAttribute(phase2_impl, cudaFuncAttributeMaxDynamicSharedMemorySize, (int)sm2);

    const int prep_blocks = (EMB_UNITS + EMBT_UNITS + 255) / 256;
    prep_kernel<<<prep_blocks, 256>>>(emb, embt);

    phase1_kernel<<<BB, 512, sm1>>>(re, ret, mask, maskt, alias, aliast,
                                    w1, w2, w3, v, bias);

    dim3 grid2(2, (NOUT + 127) / 128, 1);
    phase2_impl<<<grid2, 256, sm2>>>(csort, out);
}